// round 1
// baseline (speedup 1.0000x reference)
#include <cuda_runtime.h>
#include <cstddef>

#define NN0 50000
#define NN1 20000
#define NN2 8000
#define NN3 3200
#define NN4 1300

// ---------------- device scratch (no allocation allowed) ----------------
__device__ float g_x0[NN0 * 32];
__device__ float g_x1[NN1 * 32];
__device__ float g_x2[NN2 * 64];
__device__ float g_x3[NN3 * 128];
__device__ float g_x4[NN4 * 256];
__device__ float g_y [NN0 * 128];   // also holds [N3,384] concat (1.23M < 6.4M)
__device__ float g_ta[NN0 * 128];
__device__ float g_tb[NN0 * 128];
__device__ float g_p1[800 * 512];   // BN partial sums   (<=782 blocks)
__device__ float g_p2[800 * 512];   // BN partial sumsq
__device__ float g_mean[2 * 512];
__device__ float g_istd[2 * 512];

// ---------------- gather-GEMM:  out[M,Cout] = sum_k X[nbr[m,k]] @ W[k] ----
// nbr == nullptr -> identity gather (dense GEMM, Koff must be 1)
// Tiles: 64x64 output, BK=16, 256 threads, 4x4 register micro-tile.
#define BM 64
#define BN 64
#define BK 16

__global__ void gconv_kernel(const float* __restrict__ X,
                             const int*   __restrict__ nbr,
                             const float* __restrict__ W,
                             const float* __restrict__ bias,
                             float* __restrict__ out,
                             int M, int Cin, int Cout, int Koff, int doRelu)
{
    __shared__ float As[BK][BM + 1];
    __shared__ float Bs[BK][BN];
    __shared__ int   rows[BM];

    const int tid = threadIdx.x;           // 0..255
    const int m0  = blockIdx.y * BM;
    const int n0  = blockIdx.x * BN;
    const int tx  = tid & 15;
    const int ty  = tid >> 4;

    float acc[4][4] = {};
    const int kchunks = (Cin + BK - 1) / BK;

    for (int k = 0; k < Koff; ++k) {
        if (tid < BM) {
            int m = m0 + tid;
            int r = 0;
            if (m < M) r = nbr ? nbr[(size_t)m * Koff + k] : m;
            rows[tid] = r;
        }
        __syncthreads();

        const float* Wk = W + (size_t)k * Cin * Cout;

        for (int cc = 0; cc < kchunks; ++cc) {
            const int ci0 = cc * BK;
            // A tile: 64 rows x 16 chans (gathered)
            #pragma unroll
            for (int e = 0; e < 4; ++e) {
                int idx = tid + e * 256;
                int ki  = idx & 15;
                int mi  = idx >> 4;
                int ci  = ci0 + ki;
                float v = 0.f;
                if (ci < Cin && (m0 + mi) < M)
                    v = X[(size_t)rows[mi] * Cin + ci];
                As[ki][mi] = v;
            }
            // B tile: 16 chans x 64 couts
            #pragma unroll
            for (int e = 0; e < 4; ++e) {
                int idx = tid + e * 256;
                int ni  = idx & 63;
                int ki  = idx >> 6;
                int ci  = ci0 + ki;
                float v = 0.f;
                if (ci < Cin && (n0 + ni) < Cout)
                    v = Wk[(size_t)ci * Cout + (n0 + ni)];
                Bs[ki][ni] = v;
            }
            __syncthreads();

            #pragma unroll
            for (int kk = 0; kk < BK; ++kk) {
                float a[4], b[4];
                #pragma unroll
                for (int i = 0; i < 4; ++i) a[i] = As[kk][ty + 16 * i];
                #pragma unroll
                for (int j = 0; j < 4; ++j) b[j] = Bs[kk][tx + 16 * j];
                #pragma unroll
                for (int i = 0; i < 4; ++i)
                    #pragma unroll
                    for (int j = 0; j < 4; ++j)
                        acc[i][j] += a[i] * b[j];
            }
            __syncthreads();
        }
    }

    #pragma unroll
    for (int i = 0; i < 4; ++i) {
        int m = m0 + ty + 16 * i;
        if (m >= M) continue;
        #pragma unroll
        for (int j = 0; j < 4; ++j) {
            int n = n0 + tx + 16 * j;
            if (n >= Cout) continue;
            float v = acc[i][j];
            if (bias) v += bias[n];
            if (doRelu) v = fmaxf(v, 0.f);
            out[(size_t)m * Cout + n] = v;
        }
    }
}

// ---------------- BN stats: per-block partials (deterministic) ------------
__global__ void bn_stats_kernel(const float* __restrict__ x, int M, int C,
                                float* __restrict__ p1, float* __restrict__ p2)
{
    const int r0   = blockIdx.x * 64;
    const int rend = min(r0 + 64, M);
    const int c0 = threadIdx.x;
    const int c1 = threadIdx.x + 256;
    float a0 = 0.f, q0 = 0.f, a1 = 0.f, q1 = 0.f;
    for (int r = r0; r < rend; ++r) {
        const float* row = x + (size_t)r * C;
        if (c0 < C) { float v = row[c0]; a0 += v; q0 += v * v; }
        if (c1 < C) { float v = row[c1]; a1 += v; q1 += v * v; }
    }
    float* o1 = p1 + (size_t)blockIdx.x * 512;
    float* o2 = p2 + (size_t)blockIdx.x * 512;
    if (c0 < C) { o1[c0] = a0; o2[c0] = q0; }
    if (c1 < C) { o1[c1] = a1; o2[c1] = q1; }
}

__global__ void bn_finalize_kernel(const float* __restrict__ p1,
                                   const float* __restrict__ p2,
                                   int nblk, int M, int C,
                                   float* __restrict__ mean,
                                   float* __restrict__ istd)
{
    int c = blockIdx.x * blockDim.x + threadIdx.x;
    if (c >= C) return;
    float s1 = 0.f, s2 = 0.f;
    for (int b = 0; b < nblk; ++b) {
        s1 += p1[(size_t)b * 512 + c];
        s2 += p2[(size_t)b * 512 + c];
    }
    float m = s1 / (float)M;
    float v = s2 / (float)M - m * m;
    mean[c] = m;
    istd[c] = rsqrtf(v + 1e-5f);
}

// mode 0: out = relu((a-m0)*i0)
// mode 1: out = relu((a-m0)*i0 + b)              (identity residual)
// mode 2: out = relu((a-m0)*i0 + (b-m1)*i1)      (bn shortcut residual)
__global__ void bn_apply_kernel(const float* __restrict__ a,
                                const float* __restrict__ b,
                                const float* __restrict__ m0, const float* __restrict__ i0,
                                const float* __restrict__ m1, const float* __restrict__ i1,
                                float* __restrict__ out, int M, int C, int mode)
{
    size_t i = (size_t)blockIdx.x * blockDim.x + threadIdx.x;
    size_t total = (size_t)M * C;
    if (i >= total) return;
    int c = (int)(i % (size_t)C);
    float v = (a[i] - m0[c]) * i0[c];
    if (mode == 1)      v += b[i];
    else if (mode == 2) v += (b[i] - m1[c]) * i1[c];
    out[i] = fmaxf(v, 0.f);
}

// ---------------- transposed conv: out[m] = X[parent[m]] @ W[off[m]] -----
__global__ void deconv_kernel(const float* __restrict__ X,
                              const int* __restrict__ parent,
                              const int* __restrict__ koff,
                              const float* __restrict__ W,
                              float* __restrict__ out,
                              int M, int Cin, int Cout)
{
    __shared__ float xs[256];
    const int m = blockIdx.x;
    const int p = parent[m];
    const int o = koff[m];
    for (int c = threadIdx.x; c < Cin; c += blockDim.x)
        xs[c] = X[(size_t)p * Cin + c];
    __syncthreads();
    const float* Wk = W + (size_t)o * Cin * Cout;
    for (int n = threadIdx.x; n < Cout; n += blockDim.x) {
        float acc = 0.f;
        for (int ci = 0; ci < Cin; ++ci)
            acc += xs[ci] * Wk[(size_t)ci * Cout + n];
        out[(size_t)m * Cout + n] = acc;
    }
}

__global__ void concat_kernel(const float* __restrict__ a, const float* __restrict__ b,
                              float* __restrict__ out, int M, int Ca, int Cb)
{
    size_t i = (size_t)blockIdx.x * blockDim.x + threadIdx.x;
    const int C = Ca + Cb;
    size_t total = (size_t)M * C;
    if (i >= total) return;
    int r = (int)(i / (size_t)C);
    int c = (int)(i % (size_t)C);
    out[i] = (c < Ca) ? a[(size_t)r * Ca + c] : b[(size_t)r * Cb + (c - Ca)];
}

// ---------------- host-side orchestration --------------------------------
static float *TA, *TB, *Y, *X0, *X1, *X2, *X3, *X4, *P1, *P2, *MEAN, *ISTD;
static const float* gP;
static size_t gOff;

static inline const float* takeP(size_t n) { const float* w = gP + gOff; gOff += n; return w; }

static void run_conv(const float* X, const int* nbr, const float* W, float* out,
                     int M, int Cin, int Cout, int K,
                     const float* bias = nullptr, int relu = 0)
{
    dim3 grid((Cout + BN - 1) / BN, (M + BM - 1) / BM);
    gconv_kernel<<<grid, 256>>>(X, nbr, W, bias, out, M, Cin, Cout, K, relu);
}

static void run_bn(const float* a, int M, int C, int slot)
{
    int nb = (M + 63) / 64;
    bn_stats_kernel<<<nb, 256>>>(a, M, C, P1, P2);
    bn_finalize_kernel<<<(C + 127) / 128, 128>>>(P1, P2, nb, M, C,
                                                 MEAN + slot * 512, ISTD + slot * 512);
}

static void run_apply(const float* a, const float* b, float* out, int M, int C, int mode)
{
    size_t total = (size_t)M * C;
    bn_apply_kernel<<<(unsigned)((total + 255) / 256), 256>>>(
        a, b, MEAN, ISTD, MEAN + 512, ISTD + 512, out, M, C, mode);
}

static void cbr(const float* x, const int* nbr, int M, int Cin, int Cout, int K, float* out)
{
    const float* w = takeP((size_t)K * Cin * Cout);
    run_conv(x, nbr, w, TA, M, Cin, Cout, K);
    run_bn(TA, M, Cout, 0);
    run_apply(TA, nullptr, out, M, Cout, 0);
}

static void resblock(const float* x, const int* nbr, int M, int ci, int co, float* out)
{
    const float* w1 = takeP((size_t)27 * ci * co);
    const float* w2 = takeP((size_t)27 * co * co);
    run_conv(x, nbr, w1, TA, M, ci, co, 27);
    run_bn(TA, M, co, 0);
    run_apply(TA, nullptr, TB, M, co, 0);
    run_conv(TB, nbr, w2, TA, M, co, co, 27);
    run_bn(TA, M, co, 0);
    if (ci != co) {
        const float* ws = takeP((size_t)ci * co);
        run_conv(x, nullptr, ws, TB, M, ci, co, 1);
        run_bn(TB, M, co, 1);
        run_apply(TA, TB, out, M, co, 2);
    } else {
        run_apply(TA, x, out, M, co, 1);
    }
}

static void up_block(const float* x, const int* par, const int* off, int M,
                     int Cin, int Cout, const float* skip, int Cskip, float* out)
{
    const float* w = takeP((size_t)8 * Cin * Cout);
    deconv_kernel<<<M, 128>>>(x, par, off, w, TA, M, Cin, Cout);
    run_bn(TA, M, Cout, 0);
    run_apply(TA, nullptr, TB, M, Cout, 0);
    size_t total = (size_t)M * (Cout + Cskip);
    concat_kernel<<<(unsigned)((total + 255) / 256), 256>>>(TB, skip, out, M, Cout, Cskip);
}

extern "C" void kernel_launch(void* const* d_in, const int* in_sizes, int n_in,
                              void* d_out, int out_size)
{
    const float* x    = (const float*)d_in[0];
    const int* nbr0   = (const int*)d_in[1];
    const int* nbr1   = (const int*)d_in[2];
    const int* nbr2   = (const int*)d_in[3];
    const int* nbr3   = (const int*)d_in[4];
    const int* nbr4   = (const int*)d_in[5];
    const int* d1     = (const int*)d_in[6];
    const int* d2     = (const int*)d_in[7];
    const int* d3     = (const int*)d_in[8];
    const int* d4     = (const int*)d_in[9];
    const int* u1p    = (const int*)d_in[10];
    const int* u1o    = (const int*)d_in[11];
    const int* u2p    = (const int*)d_in[12];
    const int* u2o    = (const int*)d_in[13];
    const int* u3p    = (const int*)d_in[14];
    const int* u3o    = (const int*)d_in[15];
    const int* u4p    = (const int*)d_in[16];
    const int* u4o    = (const int*)d_in[17];
    gP = (const float*)d_in[18];
    gOff = 0;

    cudaGetSymbolAddress((void**)&X0,   g_x0);
    cudaGetSymbolAddress((void**)&X1,   g_x1);
    cudaGetSymbolAddress((void**)&X2,   g_x2);
    cudaGetSymbolAddress((void**)&X3,   g_x3);
    cudaGetSymbolAddress((void**)&X4,   g_x4);
    cudaGetSymbolAddress((void**)&Y,    g_y);
    cudaGetSymbolAddress((void**)&TA,   g_ta);
    cudaGetSymbolAddress((void**)&TB,   g_tb);
    cudaGetSymbolAddress((void**)&P1,   g_p1);
    cudaGetSymbolAddress((void**)&P2,   g_p2);
    cudaGetSymbolAddress((void**)&MEAN, g_mean);
    cudaGetSymbolAddress((void**)&ISTD, g_istd);

    // ---- stem (N0) ----
    cbr(x,  nbr0, NN0, 4,  32, 27, X0);
    cbr(X0, nbr0, NN0, 32, 32, 27, X0);

    // ---- stage1 (N1) ----
    cbr(X0, d1, NN1, 32, 32, 8, Y);
    resblock(Y, nbr1, NN1, 32, 32, Y);
    resblock(Y, nbr1, NN1, 32, 32, X1);

    // ---- stage2 (N2) ----
    cbr(X1, d2, NN2, 32, 32, 8, Y);
    resblock(Y, nbr2, NN2, 32, 64, Y);
    resblock(Y, nbr2, NN2, 64, 64, X2);

    // ---- stage3 (N3) ----
    cbr(X2, d3, NN3, 64, 64, 8, Y);
    resblock(Y, nbr3, NN3, 64, 128, Y);
    resblock(Y, nbr3, NN3, 128, 128, X3);

    // ---- stage4 (N4) ----
    cbr(X3, d4, NN4, 128, 128, 8, Y);
    resblock(Y, nbr4, NN4, 128, 256, Y);
    resblock(Y, nbr4, NN4, 256, 256, X4);

    // ---- up1 (N3) ----
    up_block(X4, u1p, u1o, NN3, 256, 256, X3, 128, Y);
    resblock(Y, nbr3, NN3, 384, 256, Y);
    resblock(Y, nbr3, NN3, 256, 256, Y);

    // ---- up2 (N2) ----
    up_block(Y, u2p, u2o, NN2, 256, 128, X2, 64, Y);
    resblock(Y, nbr2, NN2, 192, 128, Y);
    resblock(Y, nbr2, NN2, 128, 128, Y);

    // ---- up3 (N1) ----
    up_block(Y, u3p, u3o, NN1, 128, 96, X1, 32, Y);
    resblock(Y, nbr1, NN1, 128, 96, Y);
    resblock(Y, nbr1, NN1, 96, 96, Y);

    // ---- up4 (N0) ----
    up_block(Y, u4p, u4o, NN0, 96, 96, X0, 32, Y);
    resblock(Y, nbr0, NN0, 128, 96, Y);
    resblock(Y, nbr0, NN0, 96, 96, Y);

    // ---- head ----
    const float* wc = takeP((size_t)96 * 19);
    const float* bc = takeP(19);
    const float* w1 = takeP((size_t)96 * 96);
    const float* b1 = takeP(96);
    const float* w2 = takeP((size_t)96 * 128);
    const float* b2 = takeP(128);

    float* out = (float*)d_out;
    // logits [N0,19]
    run_conv(Y, nullptr, wc, out, NN0, 96, 19, 1, bc, 0);
    // feat = relu(Y@w1+b1) @ w2 + b2  -> [N0,128]
    run_conv(Y,  nullptr, w1, TA, NN0, 96, 96, 1, b1, 1);
    run_conv(TA, nullptr, w2, out + (size_t)NN0 * 19, NN0, 96, 128, 1, b2, 0);
}

// round 3
// speedup vs baseline: 1.0935x; 1.0935x over previous
#include <cuda_runtime.h>
#include <cstddef>
#include <cstdint>

#define NN0 50000
#define NN1 20000
#define NN2 8000
#define NN3 3200
#define NN4 1300

// ---------------- device scratch (no allocation allowed) ----------------
__device__ float g_x0[NN0 * 32];
__device__ float g_x1[NN1 * 32];
__device__ float g_x2[NN2 * 64];
__device__ float g_x3[NN3 * 128];
__device__ float g_x4[NN4 * 256];
__device__ float g_y [NN0 * 128];
__device__ float g_ta[NN0 * 128];
__device__ float g_tb[NN0 * 128];
__device__ float g_split[4 * 1024 * 1024];   // split-K partial outputs (16MB)
__device__ float g_p1[800 * 512];
__device__ float g_p2[800 * 512];
__device__ float g_mean[2 * 512];
__device__ float g_istd[2 * 512];

#define BK 16

// ---------------- gather-GEMM (templated tiles) ---------------------------
// out[M,Cout] = sum_{k in [k0,k1)} X[nbr[m,k]] @ W[k]   (nbr==null -> identity)
template<int TBM, int TBN, int TTM, int TTN>
__global__ __launch_bounds__(256)
void gconv_t(const float* __restrict__ X,
             const int*   __restrict__ nbr,
             const float* __restrict__ W,
             const float* __restrict__ bias,
             float* __restrict__ out,
             int M, int Cin, int Cout, int Koff, int k0, int k1, int doRelu)
{
    __shared__ float As[BK][TBM + 4];
    __shared__ float Bs[BK][TBN];
    __shared__ int   rows[TBM];

    const int tid = threadIdx.x;
    const int m0  = blockIdx.y * TBM;
    const int n0  = blockIdx.x * TBN;
    constexpr int NTX = TBN / TTN;           // threads along n
    const int tx = tid % NTX;
    const int ty = tid / NTX;

    float acc[TTM][TTN];
    #pragma unroll
    for (int i = 0; i < TTM; ++i)
        #pragma unroll
        for (int j = 0; j < TTN; ++j) acc[i][j] = 0.f;

    const int kchunks = (Cin + BK - 1) / BK;

    for (int k = k0; k < k1; ++k) {
        if (tid < TBM) {
            int m = m0 + tid;
            rows[tid] = (m < M) ? (nbr ? nbr[(size_t)m * Koff + k] : m) : 0;
        }
        __syncthreads();

        const float* Wk = W + (size_t)k * Cin * Cout;
        // vectorized B-tile path only if Wk is 16B-aligned AND Cout%4==0
        const bool bVec = (Cout % 4 == 0) && ((((uintptr_t)Wk) & 15u) == 0u);

        for (int cc = 0; cc < kchunks; ++cc) {
            const int ci0 = cc * BK;
            // ---- A tile: TBM rows x 16 chans, gathered, stored transposed
            #pragma unroll
            for (int idx = tid; idx < TBM * 4; idx += 256) {
                int mi = idx >> 2;
                int c4 = (idx & 3) << 2;
                int c  = ci0 + c4;
                float4 v = make_float4(0.f, 0.f, 0.f, 0.f);
                if (c < Cin)
                    v = *reinterpret_cast<const float4*>(X + (size_t)rows[mi] * Cin + c);
                As[c4 + 0][mi] = v.x;
                As[c4 + 1][mi] = v.y;
                As[c4 + 2][mi] = v.z;
                As[c4 + 3][mi] = v.w;
            }
            // ---- B tile: 16 chans x TBN couts
            if (bVec) {
                #pragma unroll
                for (int idx = tid; idx < 4 * TBN; idx += 256) {
                    int ni = (idx % (TBN / 4)) * 4;
                    int ki = idx / (TBN / 4);
                    int c  = ci0 + ki;
                    int n  = n0 + ni;
                    float4 v = make_float4(0.f, 0.f, 0.f, 0.f);
                    if (c < Cin && n < Cout)
                        v = *reinterpret_cast<const float4*>(Wk + (size_t)c * Cout + n);
                    *reinterpret_cast<float4*>(&Bs[ki][ni]) = v;
                }
            } else {
                #pragma unroll
                for (int idx = tid; idx < 4 * TBN; idx += 256) {
                    int ni = (idx % (TBN / 4)) * 4;
                    int ki = idx / (TBN / 4);
                    int c  = ci0 + ki;
                    #pragma unroll
                    for (int j = 0; j < 4; ++j) {
                        int n = n0 + ni + j;
                        Bs[ki][ni + j] = (c < Cin && n < Cout)
                                       ? Wk[(size_t)c * Cout + n] : 0.f;
                    }
                }
            }
            __syncthreads();

            #pragma unroll
            for (int kk = 0; kk < BK; ++kk) {
                float a[TTM], b[TTN];
                #pragma unroll
                for (int i4 = 0; i4 < TTM / 4; ++i4)
                    *reinterpret_cast<float4*>(&a[i4 * 4]) =
                        *reinterpret_cast<const float4*>(&As[kk][ty * TTM + i4 * 4]);
                #pragma unroll
                for (int j4 = 0; j4 < TTN / 4; ++j4)
                    *reinterpret_cast<float4*>(&b[j4 * 4]) =
                        *reinterpret_cast<const float4*>(&Bs[kk][tx * TTN + j4 * 4]);
                #pragma unroll
                for (int i = 0; i < TTM; ++i)
                    #pragma unroll
                    for (int j = 0; j < TTN; ++j)
                        acc[i][j] += a[i] * b[j];
            }
            __syncthreads();
        }
    }

    #pragma unroll
    for (int i = 0; i < TTM; ++i) {
        int m = m0 + ty * TTM + i;
        if (m >= M) continue;
        #pragma unroll
        for (int j = 0; j < TTN; ++j) {
            int n = n0 + tx * TTN + j;
            if (n >= Cout) continue;
            float v = acc[i][j];
            if (bias) v += bias[n];
            if (doRelu) v = fmaxf(v, 0.f);
            out[(size_t)m * Cout + n] = v;
        }
    }
}

// ordered deterministic sum of S split partials
__global__ void reduce_split_kernel(const float* __restrict__ buf,
                                    float* __restrict__ out,
                                    long long MN, int S)
{
    long long i = (long long)blockIdx.x * blockDim.x + threadIdx.x;
    if (i >= MN) return;
    float s = 0.f;
    for (int k = 0; k < S; ++k) s += buf[(size_t)k * MN + i];
    out[i] = s;
}

// ---------------- BN stats (deterministic two-phase) ----------------------
__global__ void bn_stats_kernel(const float* __restrict__ x, int M, int C,
                                float* __restrict__ p1, float* __restrict__ p2)
{
    const int r0   = blockIdx.x * 64;
    const int rend = min(r0 + 64, M);
    const int c0 = threadIdx.x;
    const int c1 = threadIdx.x + 256;
    float a0 = 0.f, q0 = 0.f, a1 = 0.f, q1 = 0.f;
    for (int r = r0; r < rend; ++r) {
        const float* row = x + (size_t)r * C;
        if (c0 < C) { float v = row[c0]; a0 += v; q0 += v * v; }
        if (c1 < C) { float v = row[c1]; a1 += v; q1 += v * v; }
    }
    float* o1 = p1 + (size_t)blockIdx.x * 512;
    float* o2 = p2 + (size_t)blockIdx.x * 512;
    if (c0 < C) { o1[c0] = a0; o2[c0] = q0; }
    if (c1 < C) { o1[c1] = a1; o2[c1] = q1; }
}

__global__ void bn_finalize_kernel(const float* __restrict__ p1,
                                   const float* __restrict__ p2,
                                   int nblk, int M, int C,
                                   float* __restrict__ mean,
                                   float* __restrict__ istd)
{
    int c = blockIdx.x * blockDim.x + threadIdx.x;
    if (c >= C) return;
    float s1 = 0.f, s2 = 0.f;
    for (int b = 0; b < nblk; ++b) {
        s1 += p1[(size_t)b * 512 + c];
        s2 += p2[(size_t)b * 512 + c];
    }
    float m = s1 / (float)M;
    float v = s2 / (float)M - m * m;
    mean[c] = m;
    istd[c] = rsqrtf(v + 1e-5f);
}

// mode 0: relu((a-m0)*i0); 1: relu(bn(a)+b); 2: relu(bn(a)+bn2(b))
__global__ void bn_apply_kernel(const float* __restrict__ a,
                                const float* __restrict__ b,
                                const float* __restrict__ m0, const float* __restrict__ i0,
                                const float* __restrict__ m1, const float* __restrict__ i1,
                                float* __restrict__ out, int M, int C, int mode)
{
    size_t i = (size_t)blockIdx.x * blockDim.x + threadIdx.x;
    size_t total = (size_t)M * C;
    if (i >= total) return;
    int c = (int)(i % (size_t)C);
    float v = (a[i] - m0[c]) * i0[c];
    if (mode == 1)      v += b[i];
    else if (mode == 2) v += (b[i] - m1[c]) * i1[c];
    out[i] = fmaxf(v, 0.f);
}

// ---------------- transposed conv ----------------------------------------
__global__ void deconv_kernel(const float* __restrict__ X,
                              const int* __restrict__ parent,
                              const int* __restrict__ koff,
                              const float* __restrict__ W,
                              float* __restrict__ out,
                              int M, int Cin, int Cout)
{
    __shared__ float xs[256];
    const int m = blockIdx.x;
    const int p = parent[m];
    const int o = koff[m];
    for (int c = threadIdx.x; c < Cin; c += blockDim.x)
        xs[c] = X[(size_t)p * Cin + c];
    __syncthreads();
    const float* Wk = W + (size_t)o * Cin * Cout;
    for (int n = threadIdx.x; n < Cout; n += blockDim.x) {
        float acc = 0.f;
        #pragma unroll 4
        for (int ci = 0; ci < Cin; ++ci)
            acc += xs[ci] * Wk[(size_t)ci * Cout + n];
        out[(size_t)m * Cout + n] = acc;
    }
}

__global__ void concat_kernel(const float* __restrict__ a, const float* __restrict__ b,
                              float* __restrict__ out, int M, int Ca, int Cb)
{
    size_t i = (size_t)blockIdx.x * blockDim.x + threadIdx.x;
    const int C = Ca + Cb;
    size_t total = (size_t)M * C;
    if (i >= total) return;
    int r = (int)(i / (size_t)C);
    int c = (int)(i % (size_t)C);
    out[i] = (c < Ca) ? a[(size_t)r * Ca + c] : b[(size_t)r * Cb + (c - Ca)];
}

// ---------------- host-side orchestration --------------------------------
static float *TA, *TB, *Y, *X0, *X1, *X2, *X3, *X4, *SPL, *P1, *P2, *MEAN, *ISTD;
static const float* gP;
static size_t gOff;

static inline const float* takeP(size_t n) { const float* w = gP + gOff; gOff += n; return w; }
static inline int cdiv(int a, int b) { return (a + b - 1) / b; }

static void launch_cfg(int id, dim3 grid,
                       const float* X, const int* nbr, const float* W,
                       const float* bias, float* out,
                       int M, int Cin, int Cout, int K, int k0, int k1, int relu)
{
    switch (id) {
    case 0: gconv_t<128, 64, 8, 4><<<grid, 256>>>(X, nbr, W, bias, out, M, Cin, Cout, K, k0, k1, relu); break;
    case 1: gconv_t< 64, 64, 4, 4><<<grid, 256>>>(X, nbr, W, bias, out, M, Cin, Cout, K, k0, k1, relu); break;
    case 2: gconv_t< 64,128, 4, 8><<<grid, 256>>>(X, nbr, W, bias, out, M, Cin, Cout, K, k0, k1, relu); break;
    default: gconv_t<128, 32, 4, 4><<<grid, 256>>>(X, nbr, W, bias, out, M, Cin, Cout, K, k0, k1, relu); break;
    }
}

static void run_conv(const float* X, const int* nbr, const float* W, float* out,
                     int M, int Cin, int Cout, int K,
                     const float* bias = nullptr, int relu = 0)
{
    int id, bm, bn;
    if (Cout <= 32)          { id = 3; bm = 128; bn = 32;  }
    else if (M >= 16000)     { id = 0; bm = 128; bn = 64;  }
    else if (Cout >= 128)    { id = 2; bm = 64;  bn = 128; }
    else                     { id = 1; bm = 64;  bn = 64;  }

    dim3 grid(cdiv(Cout, bn), cdiv(M, bm));
    int blocks = grid.x * grid.y;

    int S = 1, kper = K;
    if (nbr && K > 1 && blocks < 296) {
        S = (296 + blocks - 1) / blocks;
        if (S > K) S = K;
        kper = (K + S - 1) / S;
        S = (K + kper - 1) / kper;
    }
    if (S == 1) {
        launch_cfg(id, grid, X, nbr, W, bias, out, M, Cin, Cout, K, 0, K, relu);
    } else {
        long long MN = (long long)M * Cout;
        for (int s = 0; s < S; ++s) {
            int k0 = s * kper;
            int k1 = k0 + kper; if (k1 > K) k1 = K;
            launch_cfg(id, grid, X, nbr, W, nullptr, SPL + (size_t)s * MN,
                       M, Cin, Cout, K, k0, k1, 0);
        }
        reduce_split_kernel<<<(unsigned)((MN + 255) / 256), 256>>>(SPL, out, MN, S);
    }
}

static void run_bn(const float* a, int M, int C, int slot)
{
    int nb = cdiv(M, 64);
    bn_stats_kernel<<<nb, 256>>>(a, M, C, P1, P2);
    bn_finalize_kernel<<<cdiv(C, 128), 128>>>(P1, P2, nb, M, C,
                                              MEAN + slot * 512, ISTD + slot * 512);
}

static void run_apply(const float* a, const float* b, float* out, int M, int C, int mode)
{
    size_t total = (size_t)M * C;
    bn_apply_kernel<<<(unsigned)((total + 255) / 256), 256>>>(
        a, b, MEAN, ISTD, MEAN + 512, ISTD + 512, out, M, C, mode);
}

static void cbr(const float* x, const int* nbr, int M, int Cin, int Cout, int K, float* out)
{
    const float* w = takeP((size_t)K * Cin * Cout);
    run_conv(x, nbr, w, TA, M, Cin, Cout, K);
    run_bn(TA, M, Cout, 0);
    run_apply(TA, nullptr, out, M, Cout, 0);
}

static void resblock(const float* x, const int* nbr, int M, int ci, int co, float* out)
{
    const float* w1 = takeP((size_t)27 * ci * co);
    const float* w2 = takeP((size_t)27 * co * co);
    run_conv(x, nbr, w1, TA, M, ci, co, 27);
    run_bn(TA, M, co, 0);
    run_apply(TA, nullptr, TB, M, co, 0);
    run_conv(TB, nbr, w2, TA, M, co, co, 27);
    run_bn(TA, M, co, 0);
    if (ci != co) {
        const float* ws = takeP((size_t)ci * co);
        run_conv(x, nullptr, ws, TB, M, ci, co, 1);
        run_bn(TB, M, co, 1);
        run_apply(TA, TB, out, M, co, 2);
    } else {
        run_apply(TA, x, out, M, co, 1);
    }
}

static void up_block(const float* x, const int* par, const int* off, int M,
                     int Cin, int Cout, const float* skip, int Cskip, float* out)
{
    const float* w = takeP((size_t)8 * Cin * Cout);
    deconv_kernel<<<M, 128>>>(x, par, off, w, TA, M, Cin, Cout);
    run_bn(TA, M, Cout, 0);
    run_apply(TA, nullptr, TB, M, Cout, 0);
    size_t total = (size_t)M * (Cout + Cskip);
    concat_kernel<<<(unsigned)((total + 255) / 256), 256>>>(TB, skip, out, M, Cout, Cskip);
}

extern "C" void kernel_launch(void* const* d_in, const int* in_sizes, int n_in,
                              void* d_out, int out_size)
{
    const float* x    = (const float*)d_in[0];
    const int* nbr0   = (const int*)d_in[1];
    const int* nbr1   = (const int*)d_in[2];
    const int* nbr2   = (const int*)d_in[3];
    const int* nbr3   = (const int*)d_in[4];
    const int* nbr4   = (const int*)d_in[5];
    const int* d1     = (const int*)d_in[6];
    const int* d2     = (const int*)d_in[7];
    const int* d3     = (const int*)d_in[8];
    const int* d4     = (const int*)d_in[9];
    const int* u1p    = (const int*)d_in[10];
    const int* u1o    = (const int*)d_in[11];
    const int* u2p    = (const int*)d_in[12];
    const int* u2o    = (const int*)d_in[13];
    const int* u3p    = (const int*)d_in[14];
    const int* u3o    = (const int*)d_in[15];
    const int* u4p    = (const int*)d_in[16];
    const int* u4o    = (const int*)d_in[17];
    gP = (const float*)d_in[18];
    gOff = 0;

    cudaGetSymbolAddress((void**)&X0,   g_x0);
    cudaGetSymbolAddress((void**)&X1,   g_x1);
    cudaGetSymbolAddress((void**)&X2,   g_x2);
    cudaGetSymbolAddress((void**)&X3,   g_x3);
    cudaGetSymbolAddress((void**)&X4,   g_x4);
    cudaGetSymbolAddress((void**)&Y,    g_y);
    cudaGetSymbolAddress((void**)&TA,   g_ta);
    cudaGetSymbolAddress((void**)&TB,   g_tb);
    cudaGetSymbolAddress((void**)&SPL,  g_split);
    cudaGetSymbolAddress((void**)&P1,   g_p1);
    cudaGetSymbolAddress((void**)&P2,   g_p2);
    cudaGetSymbolAddress((void**)&MEAN, g_mean);
    cudaGetSymbolAddress((void**)&ISTD, g_istd);

    // ---- stem (N0) ----
    cbr(x,  nbr0, NN0, 4,  32, 27, X0);
    cbr(X0, nbr0, NN0, 32, 32, 27, X0);

    // ---- stage1 (N1) ----
    cbr(X0, d1, NN1, 32, 32, 8, Y);
    resblock(Y, nbr1, NN1, 32, 32, Y);
    resblock(Y, nbr1, NN1, 32, 32, X1);

    // ---- stage2 (N2) ----
    cbr(X1, d2, NN2, 32, 32, 8, Y);
    resblock(Y, nbr2, NN2, 32, 64, Y);
    resblock(Y, nbr2, NN2, 64, 64, X2);

    // ---- stage3 (N3) ----
    cbr(X2, d3, NN3, 64, 64, 8, Y);
    resblock(Y, nbr3, NN3, 64, 128, Y);
    resblock(Y, nbr3, NN3, 128, 128, X3);

    // ---- stage4 (N4) ----
    cbr(X3, d4, NN4, 128, 128, 8, Y);
    resblock(Y, nbr4, NN4, 128, 256, Y);
    resblock(Y, nbr4, NN4, 256, 256, X4);

    // ---- up1 (N3) ----
    up_block(X4, u1p, u1o, NN3, 256, 256, X3, 128, Y);
    resblock(Y, nbr3, NN3, 384, 256, Y);
    resblock(Y, nbr3, NN3, 256, 256, Y);

    // ---- up2 (N2) ----
    up_block(Y, u2p, u2o, NN2, 256, 128, X2, 64, Y);
    resblock(Y, nbr2, NN2, 192, 128, Y);
    resblock(Y, nbr2, NN2, 128, 128, Y);

    // ---- up3 (N1) ----
    up_block(Y, u3p, u3o, NN1, 128, 96, X1, 32, Y);
    resblock(Y, nbr1, NN1, 128, 96, Y);
    resblock(Y, nbr1, NN1, 96, 96, Y);

    // ---- up4 (N0) ----
    up_block(Y, u4p, u4o, NN0, 96, 96, X0, 32, Y);
    resblock(Y, nbr0, NN0, 128, 96, Y);
    resblock(Y, nbr0, NN0, 96, 96, Y);

    // ---- head ----
    const float* wc = takeP((size_t)96 * 19);
    const float* bc = takeP(19);
    const float* w1 = takeP((size_t)96 * 96);
    const float* b1 = takeP(96);
    const float* w2 = takeP((size_t)96 * 128);
    const float* b2 = takeP(128);

    float* out = (float*)d_out;
    run_conv(Y, nullptr, wc, out, NN0, 96, 19, 1, bc, 0);
    run_conv(Y,  nullptr, w1, TA, NN0, 96, 96, 1, b1, 1);
    run_conv(TA, nullptr, w2, out + (size_t)NN0 * 19, NN0, 96, 128, 1, b2, 0);
}

// round 4
// speedup vs baseline: 1.3401x; 1.2255x over previous
#include <cuda_runtime.h>
#include <cstddef>
#include <cstdint>

#define NN0 50000
#define NN1 20000
#define NN2 8000
#define NN3 3200
#define NN4 1300

// ---------------- device scratch (no allocation allowed) ----------------
__device__ float g_x0[NN0 * 32];
__device__ float g_x1[NN1 * 32];
__device__ float g_x2[NN2 * 64];
__device__ float g_x3[NN3 * 128];
__device__ float g_x4[NN4 * 256];
__device__ float g_y [NN0 * 128];
__device__ float g_ta[NN0 * 128];
__device__ float g_tb[NN0 * 128];
__device__ float g_split[4 * 1024 * 1024];
__device__ float g_p1[800 * 512];
__device__ float g_p2[800 * 512];
__device__ float g_mean[2 * 512];
__device__ float g_istd[2 * 512];

#define BK 16

// ---------------- pipelined gather-GEMM -----------------------------------
// out[M,Cout] = sum_{k in [k0,k1)} X[nbr[m,k]] @ W[k]   (nbr==null -> identity)
// Single-sync double-buffered smem pipeline; neighbor rows precomputed.
template<int TBM, int TBN, int TTM, int TTN>
__global__ __launch_bounds__(256)
void gconv_t(const float* __restrict__ X,
             const int*   __restrict__ nbr,
             const float* __restrict__ W,
             const float* __restrict__ bias,
             float* __restrict__ out,
             int M, int Cin, int Cout, int Koff, int k0, int k1, int doRelu)
{
    constexpr int AV  = (TBM * 4 + 255) / 256;   // float4 A loads / thread / stage
    constexpr int BV  = (4 * TBN + 255) / 256;   // float4 B loads / thread / stage
    constexpr int NTX = TBN / TTN;

    __shared__ float As[2][BK][TBM + 4];
    __shared__ float Bs[2][BK][TBN];
    __shared__ int   rows[27][TBM];

    const int tid = threadIdx.x;
    const int m0  = blockIdx.y * TBM;
    const int n0  = blockIdx.x * TBN;
    const int tx  = tid % NTX;
    const int ty  = tid / NTX;

    const int nk      = k1 - k0;
    const int kchunks = (Cin + BK - 1) / BK;
    const int nIter   = nk * kchunks;
    const bool bVec = (Cout % 4 == 0) && ((((uintptr_t)W) & 15u) == 0u)
                      && (((Cin * Cout) & 3) == 0);

    // precompute gathered row indices for every kernel offset
    for (int idx = tid; idx < nk * TBM; idx += 256) {
        int kk = idx / TBM, mi = idx - kk * TBM;
        int m  = m0 + mi;
        rows[kk][mi] = (m < M) ? (nbr ? nbr[(size_t)m * Koff + k0 + kk] : m) : 0;
    }
    __syncthreads();

    float acc[TTM][TTN];
    #pragma unroll
    for (int i = 0; i < TTM; ++i)
        #pragma unroll
        for (int j = 0; j < TTN; ++j) acc[i][j] = 0.f;

    float4 aR[AV], bR[BV];

    auto loadStage = [&](int t) {
        int k   = t / kchunks;
        int cc  = t - k * kchunks;
        int ci0 = cc * BK;
        const float* Wk = W + (size_t)(k0 + k) * Cin * Cout;
        #pragma unroll
        for (int v = 0; v < AV; ++v) {
            int idx = tid + v * 256;
            float4 val = make_float4(0.f, 0.f, 0.f, 0.f);
            if (idx < TBM * 4) {
                int mi = idx >> 2;
                int c  = ci0 + ((idx & 3) << 2);
                if (c < Cin)
                    val = *reinterpret_cast<const float4*>(
                              X + (size_t)rows[k][mi] * Cin + c);
            }
            aR[v] = val;
        }
        if (bVec) {
            #pragma unroll
            for (int v = 0; v < BV; ++v) {
                int idx = tid + v * 256;
                float4 val = make_float4(0.f, 0.f, 0.f, 0.f);
                if (idx < 4 * TBN) {
                    int ni = (idx % (TBN / 4)) * 4;
                    int ki = idx / (TBN / 4);
                    int c  = ci0 + ki;
                    int n  = n0 + ni;
                    if (c < Cin && n < Cout)
                        val = *reinterpret_cast<const float4*>(
                                  Wk + (size_t)c * Cout + n);
                }
                bR[v] = val;
            }
        } else {
            #pragma unroll
            for (int v = 0; v < BV; ++v) {
                int idx = tid + v * 256;
                float4 val = make_float4(0.f, 0.f, 0.f, 0.f);
                if (idx < 4 * TBN) {
                    int ni = (idx % (TBN / 4)) * 4;
                    int ki = idx / (TBN / 4);
                    int c  = ci0 + ki;
                    if (c < Cin) {
                        const float* p = Wk + (size_t)c * Cout;
                        int n = n0 + ni;
                        if (n + 0 < Cout) val.x = p[n + 0];
                        if (n + 1 < Cout) val.y = p[n + 1];
                        if (n + 2 < Cout) val.z = p[n + 2];
                        if (n + 3 < Cout) val.w = p[n + 3];
                    }
                }
                bR[v] = val;
            }
        }
    };

    auto storeStage = [&](int s) {
        #pragma unroll
        for (int v = 0; v < AV; ++v) {
            int idx = tid + v * 256;
            if (idx < TBM * 4) {
                int mi = idx >> 2;
                int c4 = (idx & 3) << 2;
                As[s][c4 + 0][mi] = aR[v].x;
                As[s][c4 + 1][mi] = aR[v].y;
                As[s][c4 + 2][mi] = aR[v].z;
                As[s][c4 + 3][mi] = aR[v].w;
            }
        }
        #pragma unroll
        for (int v = 0; v < BV; ++v) {
            int idx = tid + v * 256;
            if (idx < 4 * TBN) {
                int ni = (idx % (TBN / 4)) * 4;
                int ki = idx / (TBN / 4);
                *reinterpret_cast<float4*>(&Bs[s][ki][ni]) = bR[v];
            }
        }
    };

    auto computeStage = [&](int s) {
        #pragma unroll
        for (int kk = 0; kk < BK; ++kk) {
            float a[TTM], b[TTN];
            #pragma unroll
            for (int i4 = 0; i4 < TTM / 4; ++i4)
                *reinterpret_cast<float4*>(&a[i4 * 4]) =
                    *reinterpret_cast<const float4*>(&As[s][kk][ty * TTM + i4 * 4]);
            if constexpr (TTN % 4 == 0) {
                #pragma unroll
                for (int j4 = 0; j4 < TTN / 4; ++j4)
                    *reinterpret_cast<float4*>(&b[j4 * 4]) =
                        *reinterpret_cast<const float4*>(&Bs[s][kk][tx * TTN + j4 * 4]);
            } else {
                #pragma unroll
                for (int j2 = 0; j2 < TTN / 2; ++j2)
                    *reinterpret_cast<float2*>(&b[j2 * 2]) =
                        *reinterpret_cast<const float2*>(&Bs[s][kk][tx * TTN + j2 * 2]);
            }
            #pragma unroll
            for (int i = 0; i < TTM; ++i)
                #pragma unroll
                for (int j = 0; j < TTN; ++j)
                    acc[i][j] += a[i] * b[j];
        }
    };

    loadStage(0);
    storeStage(0);
    __syncthreads();

    for (int t = 0; t < nIter; ++t) {
        int cur = t & 1;
        if (t + 1 < nIter) loadStage(t + 1);   // global loads in flight
        computeStage(cur);                      // hides their latency
        if (t + 1 < nIter) storeStage(cur ^ 1);
        __syncthreads();                        // single barrier per stage
    }

    #pragma unroll
    for (int i = 0; i < TTM; ++i) {
        int m = m0 + ty * TTM + i;
        if (m >= M) continue;
        #pragma unroll
        for (int j = 0; j < TTN; ++j) {
            int n = n0 + tx * TTN + j;
            if (n >= Cout) continue;
            float v = acc[i][j];
            if (bias) v += bias[n];
            if (doRelu) v = fmaxf(v, 0.f);
            out[(size_t)m * Cout + n] = v;
        }
    }
}

// ordered deterministic sum of S split partials
__global__ void reduce_split_kernel(const float* __restrict__ buf,
                                    float* __restrict__ out,
                                    long long MN, int S)
{
    long long i = (long long)blockIdx.x * blockDim.x + threadIdx.x;
    if (i >= MN) return;
    float s = 0.f;
    for (int k = 0; k < S; ++k) s += buf[(size_t)k * MN + i];
    out[i] = s;
}

// ---------------- BN stats (deterministic two-phase) ----------------------
__global__ void bn_stats_kernel(const float* __restrict__ x, int M, int C,
                                float* __restrict__ p1, float* __restrict__ p2)
{
    const int r0   = blockIdx.x * 64;
    const int rend = min(r0 + 64, M);
    const int c0 = threadIdx.x;
    const int c1 = threadIdx.x + 256;
    float a0 = 0.f, q0 = 0.f, a1 = 0.f, q1 = 0.f;
    for (int r = r0; r < rend; ++r) {
        const float* row = x + (size_t)r * C;
        if (c0 < C) { float v = row[c0]; a0 += v; q0 += v * v; }
        if (c1 < C) { float v = row[c1]; a1 += v; q1 += v * v; }
    }
    float* o1 = p1 + (size_t)blockIdx.x * 512;
    float* o2 = p2 + (size_t)blockIdx.x * 512;
    if (c0 < C) { o1[c0] = a0; o2[c0] = q0; }
    if (c1 < C) { o1[c1] = a1; o2[c1] = q1; }
}

__global__ void bn_finalize_kernel(const float* __restrict__ p1,
                                   const float* __restrict__ p2,
                                   int nblk, int M, int C,
                                   float* __restrict__ mean,
                                   float* __restrict__ istd)
{
    int c = blockIdx.x * blockDim.x + threadIdx.x;
    if (c >= C) return;
    float s1 = 0.f, s2 = 0.f;
    for (int b = 0; b < nblk; ++b) {
        s1 += p1[(size_t)b * 512 + c];
        s2 += p2[(size_t)b * 512 + c];
    }
    float m = s1 / (float)M;
    float v = s2 / (float)M - m * m;
    mean[c] = m;
    istd[c] = rsqrtf(v + 1e-5f);
}

// mode 0: relu((a-m0)*i0); 1: relu(bn(a)+b); 2: relu(bn(a)+bn2(b))
__global__ void bn_apply_kernel(const float* __restrict__ a,
                                const float* __restrict__ b,
                                const float* __restrict__ m0, const float* __restrict__ i0,
                                const float* __restrict__ m1, const float* __restrict__ i1,
                                float* __restrict__ out, int M, int C, int mode)
{
    size_t i = (size_t)blockIdx.x * blockDim.x + threadIdx.x;
    size_t total = (size_t)M * C;
    if (i >= total) return;
    int c = (int)(i % (size_t)C);
    float v = (a[i] - m0[c]) * i0[c];
    if (mode == 1)      v += b[i];
    else if (mode == 2) v += (b[i] - m1[c]) * i1[c];
    out[i] = fmaxf(v, 0.f);
}

// ---------------- transposed conv ----------------------------------------
__global__ void deconv_kernel(const float* __restrict__ X,
                              const int* __restrict__ parent,
                              const int* __restrict__ koff,
                              const float* __restrict__ W,
                              float* __restrict__ out,
                              int M, int Cin, int Cout)
{
    __shared__ float xs[256];
    const int m = blockIdx.x;
    const int p = parent[m];
    const int o = koff[m];
    for (int c = threadIdx.x; c < Cin; c += blockDim.x)
        xs[c] = X[(size_t)p * Cin + c];
    __syncthreads();
    const float* Wk = W + (size_t)o * Cin * Cout;
    for (int n = threadIdx.x; n < Cout; n += blockDim.x) {
        float acc = 0.f;
        #pragma unroll 4
        for (int ci = 0; ci < Cin; ++ci)
            acc += xs[ci] * Wk[(size_t)ci * Cout + n];
        out[(size_t)m * Cout + n] = acc;
    }
}

__global__ void concat_kernel(const float* __restrict__ a, const float* __restrict__ b,
                              float* __restrict__ out, int M, int Ca, int Cb)
{
    size_t i = (size_t)blockIdx.x * blockDim.x + threadIdx.x;
    const int C = Ca + Cb;
    size_t total = (size_t)M * C;
    if (i >= total) return;
    int r = (int)(i / (size_t)C);
    int c = (int)(i % (size_t)C);
    out[i] = (c < Ca) ? a[(size_t)r * Ca + c] : b[(size_t)r * Cb + (c - Ca)];
}

// ---------------- host-side orchestration --------------------------------
static float *TA, *TB, *Y, *X0, *X1, *X2, *X3, *X4, *SPL, *P1, *P2, *MEAN, *ISTD;
static const float* gP;
static size_t gOff;

static inline const float* takeP(size_t n) { const float* w = gP + gOff; gOff += n; return w; }
static inline int cdiv(int a, int b) { return (a + b - 1) / b; }

static void launch_cfg(int id, dim3 grid,
                       const float* X, const int* nbr, const float* W,
                       const float* bias, float* out,
                       int M, int Cin, int Cout, int K, int k0, int k1, int relu)
{
    switch (id) {
    case 0: gconv_t<128, 64, 8, 4><<<grid, 256>>>(X, nbr, W, bias, out, M, Cin, Cout, K, k0, k1, relu); break;
    case 1: gconv_t< 64, 64, 4, 4><<<grid, 256>>>(X, nbr, W, bias, out, M, Cin, Cout, K, k0, k1, relu); break;
    case 2: gconv_t< 64,128, 4, 8><<<grid, 256>>>(X, nbr, W, bias, out, M, Cin, Cout, K, k0, k1, relu); break;
    case 3: gconv_t<128, 32, 4, 4><<<grid, 256>>>(X, nbr, W, bias, out, M, Cin, Cout, K, k0, k1, relu); break;
    default: gconv_t<64, 96, 4, 6><<<grid, 256>>>(X, nbr, W, bias, out, M, Cin, Cout, K, k0, k1, relu); break;
    }
}

static void run_conv(const float* X, const int* nbr, const float* W, float* out,
                     int M, int Cin, int Cout, int K,
                     const float* bias = nullptr, int relu = 0)
{
    int id, bm, bn;
    if (Cout == 96)          { id = 4; bm = 64;  bn = 96;  }
    else if (Cout <= 32)     { id = 3; bm = 128; bn = 32;  }
    else if (Cout >= 128)    { id = 2; bm = 64;  bn = 128; }
    else if (M >= 16000)     { id = 0; bm = 128; bn = 64;  }
    else                     { id = 1; bm = 64;  bn = 64;  }

    dim3 grid(cdiv(Cout, bn), cdiv(M, bm));
    int blocks = grid.x * grid.y;

    int S = 1, kper = K;
    if (nbr && K > 1 && blocks < 296) {
        S = (296 + blocks - 1) / blocks;
        if (S > K) S = K;
        kper = (K + S - 1) / S;
        S = (K + kper - 1) / kper;
    }
    if (S == 1) {
        launch_cfg(id, grid, X, nbr, W, bias, out, M, Cin, Cout, K, 0, K, relu);
    } else {
        long long MN = (long long)M * Cout;
        for (int s = 0; s < S; ++s) {
            int k0 = s * kper;
            int k1 = k0 + kper; if (k1 > K) k1 = K;
            launch_cfg(id, grid, X, nbr, W, nullptr, SPL + (size_t)s * MN,
                       M, Cin, Cout, K, k0, k1, 0);
        }
        reduce_split_kernel<<<(unsigned)((MN + 255) / 256), 256>>>(SPL, out, MN, S);
    }
}

static void run_bn(const float* a, int M, int C, int slot)
{
    int nb = cdiv(M, 64);
    bn_stats_kernel<<<nb, 256>>>(a, M, C, P1, P2);
    bn_finalize_kernel<<<cdiv(C, 128), 128>>>(P1, P2, nb, M, C,
                                              MEAN + slot * 512, ISTD + slot * 512);
}

static void run_apply(const float* a, const float* b, float* out, int M, int C, int mode)
{
    size_t total = (size_t)M * C;
    bn_apply_kernel<<<(unsigned)((total + 255) / 256), 256>>>(
        a, b, MEAN, ISTD, MEAN + 512, ISTD + 512, out, M, C, mode);
}

static void cbr(const float* x, const int* nbr, int M, int Cin, int Cout, int K, float* out)
{
    const float* w = takeP((size_t)K * Cin * Cout);
    run_conv(x, nbr, w, TA, M, Cin, Cout, K);
    run_bn(TA, M, Cout, 0);
    run_apply(TA, nullptr, out, M, Cout, 0);
}

static void resblock(const float* x, const int* nbr, int M, int ci, int co, float* out)
{
    const float* w1 = takeP((size_t)27 * ci * co);
    const float* w2 = takeP((size_t)27 * co * co);
    run_conv(x, nbr, w1, TA, M, ci, co, 27);
    run_bn(TA, M, co, 0);
    run_apply(TA, nullptr, TB, M, co, 0);
    run_conv(TB, nbr, w2, TA, M, co, co, 27);
    run_bn(TA, M, co, 0);
    if (ci != co) {
        const float* ws = takeP((size_t)ci * co);
        run_conv(x, nullptr, ws, TB, M, ci, co, 1);
        run_bn(TB, M, co, 1);
        run_apply(TA, TB, out, M, co, 2);
    } else {
        run_apply(TA, x, out, M, co, 1);
    }
}

static void up_block(const float* x, const int* par, const int* off, int M,
                     int Cin, int Cout, const float* skip, int Cskip, float* out)
{
    const float* w = takeP((size_t)8 * Cin * Cout);
    deconv_kernel<<<M, 128>>>(x, par, off, w, TA, M, Cin, Cout);
    run_bn(TA, M, Cout, 0);
    run_apply(TA, nullptr, TB, M, Cout, 0);
    size_t total = (size_t)M * (Cout + Cskip);
    concat_kernel<<<(unsigned)((total + 255) / 256), 256>>>(TB, skip, out, M, Cout, Cskip);
}

extern "C" void kernel_launch(void* const* d_in, const int* in_sizes, int n_in,
                              void* d_out, int out_size)
{
    const float* x    = (const float*)d_in[0];
    const int* nbr0   = (const int*)d_in[1];
    const int* nbr1   = (const int*)d_in[2];
    const int* nbr2   = (const int*)d_in[3];
    const int* nbr3   = (const int*)d_in[4];
    const int* nbr4   = (const int*)d_in[5];
    const int* d1     = (const int*)d_in[6];
    const int* d2     = (const int*)d_in[7];
    const int* d3     = (const int*)d_in[8];
    const int* d4     = (const int*)d_in[9];
    const int* u1p    = (const int*)d_in[10];
    const int* u1o    = (const int*)d_in[11];
    const int* u2p    = (const int*)d_in[12];
    const int* u2o    = (const int*)d_in[13];
    const int* u3p    = (const int*)d_in[14];
    const int* u3o    = (const int*)d_in[15];
    const int* u4p    = (const int*)d_in[16];
    const int* u4o    = (const int*)d_in[17];
    gP = (const float*)d_in[18];
    gOff = 0;

    cudaGetSymbolAddress((void**)&X0,   g_x0);
    cudaGetSymbolAddress((void**)&X1,   g_x1);
    cudaGetSymbolAddress((void**)&X2,   g_x2);
    cudaGetSymbolAddress((void**)&X3,   g_x3);
    cudaGetSymbolAddress((void**)&X4,   g_x4);
    cudaGetSymbolAddress((void**)&Y,    g_y);
    cudaGetSymbolAddress((void**)&TA,   g_ta);
    cudaGetSymbolAddress((void**)&TB,   g_tb);
    cudaGetSymbolAddress((void**)&SPL,  g_split);
    cudaGetSymbolAddress((void**)&P1,   g_p1);
    cudaGetSymbolAddress((void**)&P2,   g_p2);
    cudaGetSymbolAddress((void**)&MEAN, g_mean);
    cudaGetSymbolAddress((void**)&ISTD, g_istd);

    // ---- stem (N0) ----
    cbr(x,  nbr0, NN0, 4,  32, 27, X0);
    cbr(X0, nbr0, NN0, 32, 32, 27, X0);

    // ---- stage1 (N1) ----
    cbr(X0, d1, NN1, 32, 32, 8, Y);
    resblock(Y, nbr1, NN1, 32, 32, Y);
    resblock(Y, nbr1, NN1, 32, 32, X1);

    // ---- stage2 (N2) ----
    cbr(X1, d2, NN2, 32, 32, 8, Y);
    resblock(Y, nbr2, NN2, 32, 64, Y);
    resblock(Y, nbr2, NN2, 64, 64, X2);

    // ---- stage3 (N3) ----
    cbr(X2, d3, NN3, 64, 64, 8, Y);
    resblock(Y, nbr3, NN3, 64, 128, Y);
    resblock(Y, nbr3, NN3, 128, 128, X3);

    // ---- stage4 (N4) ----
    cbr(X3, d4, NN4, 128, 128, 8, Y);
    resblock(Y, nbr4, NN4, 128, 256, Y);
    resblock(Y, nbr4, NN4, 256, 256, X4);

    // ---- up1 (N3) ----
    up_block(X4, u1p, u1o, NN3, 256, 256, X3, 128, Y);
    resblock(Y, nbr3, NN3, 384, 256, Y);
    resblock(Y, nbr3, NN3, 256, 256, Y);

    // ---- up2 (N2) ----
    up_block(Y, u2p, u2o, NN2, 256, 128, X2, 64, Y);
    resblock(Y, nbr2, NN2, 192, 128, Y);
    resblock(Y, nbr2, NN2, 128, 128, Y);

    // ---- up3 (N1) ----
    up_block(Y, u3p, u3o, NN1, 128, 96, X1, 32, Y);
    resblock(Y, nbr1, NN1, 128, 96, Y);
    resblock(Y, nbr1, NN1, 96, 96, Y);

    // ---- up4 (N0) ----
    up_block(Y, u4p, u4o, NN0, 96, 96, X0, 32, Y);
    resblock(Y, nbr0, NN0, 128, 96, Y);
    resblock(Y, nbr0, NN0, 96, 96, Y);

    // ---- head ----
    const float* wc = takeP((size_t)96 * 19);
    const float* bc = takeP(19);
    const float* w1 = takeP((size_t)96 * 96);
    const float* b1 = takeP(96);
    const float* w2 = takeP((size_t)96 * 128);
    const float* b2 = takeP(128);

    float* out = (float*)d_out;
    run_conv(Y, nullptr, wc, out, NN0, 96, 19, 1, bc, 0);
    run_conv(Y,  nullptr, w1, TA, NN0, 96, 96, 1, b1, 1);
    run_conv(TA, nullptr, w2, out + (size_t)NN0 * 19, NN0, 96, 128, 1, b2, 0);
}